// round 14
// baseline (speedup 1.0000x reference)
#include <cuda_runtime.h>

#define N_PTS   131072
#define K_CB    1024
#define NPAIR   512          // K_CB / 2
#define D_DIM   10
#define PROW    24           // floats/pair row: 20 dims + esq0,esq1 + 2 pad
#define THREADS 128
#define NSM     148
#define GRID    (NSM * 2)    // 296 CTAs: 2/SM, 2 warps/SMSP (best known shape)
#define WARPS   (GRID * 4)   // 1184 warp-scans
#define WTILES  (N_PTS / 32) // 4096 warp-tiles of 32 points
#define W4      (WTILES - 3 * WARPS)   // 544 warps take 4 tiles, rest take 3

__constant__ float cE[NPAIR * PROW];          // 49152 B pair-packed codebook
__device__   float g_stage[NPAIR * PROW];     // staging for symbol copy
__device__   float g_partials[GRID];
__device__   unsigned int g_done = 0;

__device__ __forceinline__ unsigned long long fma2(
    unsigned long long a, unsigned long long b, unsigned long long c) {
    unsigned long long d;
    asm("fma.rn.f32x2 %0, %1, %2, %3;" : "=l"(d) : "l"(a), "l"(b), "l"(c));
    return d;
}
__device__ __forceinline__ unsigned long long dup2(float v) {
    unsigned long long r;
    asm("mov.b64 %0, {%1, %1};" : "=l"(r) : "f"(v));
    return r;
}
__device__ __forceinline__ void unpack2(unsigned long long v, float& lo, float& hi) {
    asm("mov.b64 {%0, %1}, %2;" : "=f"(lo), "=f"(hi) : "l"(v));
}

// ---- prep: pair-pack codebook + esq into staging (then copied to cE) ----
__global__ void prep_kernel(const float* __restrict__ E) {
    const int tid = threadIdx.x;
    for (int k = tid; k < K_CB; k += 256) {
        int p = k >> 1, l = k & 1;
        float s = 0.f;
        for (int j = 0; j < D_DIM; j++) {
            float e = E[k * D_DIM + j];
            g_stage[p * PROW + 2 * j + l] = e;
            s = fmaf(e, e, s);
        }
        g_stage[p * PROW + 20 + l] = s;
        if (l == 0) { g_stage[p * PROW + 22] = 0.f; g_stage[p * PROW + 23] = 0.f; }
    }
}

// Bit-exact distance pair for one code-pair row (same FMA order as hot loop).
__device__ __forceinline__ void pair_dists(int p, const unsigned long long* xd,
                                           float& d0, float& d1) {
    const ulonglong2* w = (const ulonglong2*)(cE + p * PROW);
    ulonglong2 c0 = w[0], c1 = w[1], c2 = w[2], c3 = w[3], c4 = w[4];
    unsigned long long a = w[5].x;
    a = fma2(c0.x, xd[0], a);
    a = fma2(c0.y, xd[1], a);
    a = fma2(c1.x, xd[2], a);
    a = fma2(c1.y, xd[3], a);
    a = fma2(c2.x, xd[4], a);
    a = fma2(c2.y, xd[5], a);
    a = fma2(c3.x, xd[6], a);
    a = fma2(c3.y, xd[7], a);
    a = fma2(c4.x, xd[8], a);
    a = fma2(c4.y, xd[9], a);
    unpack2(a, d0, d1);
}

// Scan all code pairs for PPT warp-tiles (this lane = one point per tile).
template <int PPT>
__device__ __forceinline__ float scan_points(
    const float* __restrict__ x, float* __restrict__ out, int wt0, int lane)
{
    int n[PPT];
    #pragma unroll
    for (int q = 0; q < PPT; q++)
        n[q] = (wt0 + q) * 32 + lane;

    unsigned long long xd[PPT][D_DIM];
    #pragma unroll
    for (int q = 0; q < PPT; q++) {
        const float* xp = x + (size_t)n[q] * D_DIM;
        #pragma unroll
        for (int j = 0; j < D_DIM; j++)
            xd[q][j] = dup2(-2.f * xp[j]);
    }

    float best[PPT];
    int   bp[PPT];
    #pragma unroll
    for (int q = 0; q < PPT; q++) { best[q] = 3.402823466e+38f; bp[q] = 0; }

    for (int p = 0; p < NPAIR; ++p) {
        const ulonglong2* w = (const ulonglong2*)(cE + p * PROW);
        ulonglong2 c0 = w[0], c1 = w[1], c2 = w[2], c3 = w[3], c4 = w[4];
        unsigned long long esq = w[5].x;

        #pragma unroll
        for (int q = 0; q < PPT; q++) {
            unsigned long long a = esq;
            a = fma2(c0.x, xd[q][0], a);
            a = fma2(c0.y, xd[q][1], a);
            a = fma2(c1.x, xd[q][2], a);
            a = fma2(c1.y, xd[q][3], a);
            a = fma2(c2.x, xd[q][4], a);
            a = fma2(c2.y, xd[q][5], a);
            a = fma2(c3.x, xd[q][6], a);
            a = fma2(c3.y, xd[q][7], a);
            a = fma2(c4.x, xd[q][8], a);
            a = fma2(c4.y, xd[q][9], a);
            float d0, d1;
            unpack2(a, d0, d1);
            float m = fminf(d0, d1);                   // FMNMX (alu pipe)
            if (m < best[q]) { best[q] = m; bp[q] = p; }   // strict < = first min
        }
    }

    // resolve winning lane (bit-exact recompute), write out + loss
    float part = 0.f;
    #pragma unroll
    for (int q = 0; q < PPT; q++) {
        int p = bp[q];
        float d0, d1;
        pair_dists(p, xd[q], d0, d1);
        int lsel = (d1 < d0) ? 1 : 0;                  // tie -> lane 0 (lower k)
        const float* er = cE + p * PROW;
        float* o = out + (size_t)n[q] * D_DIM;
        #pragma unroll
        for (int j = 0; j < D_DIM; j++) {
            float qv = er[2 * j + lsel];
            o[j] = qv;
            float lo, hi;
            unpack2(xd[q][j], lo, hi);
            float xv = -0.5f * lo;                     // exact: (-0.5)*(-2x) = x
            float dd = xv - qv;
            part += dd * dd;
        }
    }
    return part;
}

__global__ void __launch_bounds__(THREADS, 2)
vq_kernel(const float* __restrict__ x,      // [N, D]
          float* __restrict__ out)          // [N*D] quantized + loss slot
{
    __shared__ float sred[THREADS / 32];
    __shared__ int   s_last;

    const int tid  = threadIdx.x;
    const int bid  = blockIdx.x;
    const int wid  = tid >> 5;
    const int lane = tid & 31;

    // --- per-warp balanced tile assignment ---
    const int g = bid * 4 + wid;
    int wt0, cnt;
    if (g < W4) { cnt = 4; wt0 = g * 4; }
    else        { cnt = 3; wt0 = W4 * 4 + (g - W4) * 3; }

    float part;
    if (cnt == 4)
        part = scan_points<4>(x, out, wt0, lane);
    else
        part = scan_points<3>(x, out, wt0, lane);

    // --- deterministic loss: warp reduce -> CTA reduce -> per-CTA partial ---
    #pragma unroll
    for (int offr = 16; offr > 0; offr >>= 1)
        part += __shfl_down_sync(0xFFFFFFFFu, part, offr);
    if (lane == 0) sred[wid] = part;
    __syncthreads();

    if (tid == 0) {
        float s = sred[0] + sred[1] + sred[2] + sred[3];
        g_partials[bid] = s;
        __threadfence();
        unsigned int old = atomicAdd(&g_done, 1u);
        s_last = (old == GRID - 1) ? 1 : 0;
    }
    __syncthreads();

    // --- last CTA finalizes loss (fixed order -> deterministic) ---
    if (s_last) {
        __shared__ float sfin[THREADS];
        float s = 0.f;
        for (int r = tid; r < GRID; r += THREADS)   // fixed strided order
            s += g_partials[r];
        sfin[tid] = s;
        __syncthreads();
        #pragma unroll
        for (int o = THREADS / 2; o > 0; o >>= 1) {
            if (tid < o) sfin[tid] += sfin[tid + o];
            __syncthreads();
        }
        if (tid == 0) {
            out[(size_t)N_PTS * D_DIM] = sfin[0] * (1.0f / ((float)N_PTS * (float)D_DIM));
            g_done = 0;   // reset for next graph replay
        }
    }
}

extern "C" void kernel_launch(void* const* d_in, const int* in_sizes, int n_in,
                              void* d_out, int out_size) {
    const float* x = (const float*)d_in[0];   // encoder_embedding [N, D]
    const float* E = (const float*)d_in[1];   // embedding_weight  [K, D]
    float* out = (float*)d_out;

    prep_kernel<<<1, 256>>>(E);

    void* stage_ptr = nullptr;
    cudaGetSymbolAddress(&stage_ptr, g_stage);                    // no alloc
    cudaMemcpyToSymbolAsync(cE, stage_ptr, sizeof(float) * NPAIR * PROW,
                            0, cudaMemcpyDeviceToDevice);          // D2D, capturable

    vq_kernel<<<GRID, THREADS>>>(x, out);
}